// round 14
// baseline (speedup 1.0000x reference)
#include <cuda_runtime.h>
#include <cuda_fp16.h>
#include <math.h>
#include <stdint.h>

#define BB 8
#define NN 4096
#define MM 4096
#define DD 128
#define NTILES 32          // 4096 / 128 tiles along each reduced dim

// ---------------- scratch (device globals: no allocation allowed) ----------
__device__ __half g_h0[BB * NN * DD];   // normalized descriptors0, fp16
__device__ __half g_h1[BB * MM * DD];   // normalized descriptors1, fp16

__device__ float2 g_rp_v[BB * NN * NTILES];
__device__ int2   g_rp_i[BB * NN * NTILES];
__device__ float2 g_cp_v[BB * MM * NTILES];
__device__ int2   g_cp_i[BB * MM * NTILES];

__device__ int    g_m0raw[BB * NN];
__device__ int    g_m1raw[BB * MM];

// ---------------- small helpers ---------------------------------------------
__device__ __forceinline__ void push2(float v, int i,
                                      float& v0, int& i0, float& v1, int& i1) {
    if (v > v0) { v1 = v0; i1 = i0; v0 = v; i0 = i; }
    else if (v > v1) { v1 = v; i1 = i; }
}

__device__ __forceinline__ bool better(float va, int ia, float vb, int ib) {
    return (va > vb) || (va == vb && ia < ib);
}

__device__ __forceinline__ void merge2(float& v0, int& i0, float& v1, int& i1,
                                       float ov0, int oi0, float ov1, int oi1) {
    if (better(ov0, oi0, v0, i0)) {
        if (better(v0, i0, ov1, oi1)) { v1 = v0; i1 = i0; }
        else                          { v1 = ov1; i1 = oi1; }
        v0 = ov0; i0 = oi0;
    } else {
        if (better(ov0, oi0, v1, i1)) { v1 = ov0; i1 = oi0; }
    }
}

// butterfly merge step over lane-xor 'off'
__device__ __forceinline__ void bfly_merge(float& v0, int& i0, float& v1, int& i1,
                                           int off) {
    float ov0 = __shfl_xor_sync(0xFFFFFFFFu, v0, off);
    float ov1 = __shfl_xor_sync(0xFFFFFFFFu, v1, off);
    int   oi0 = __shfl_xor_sync(0xFFFFFFFFu, i0, off);
    int   oi1 = __shfl_xor_sync(0xFFFFFFFFu, i1, off);
    merge2(v0, i0, v1, i1, ov0, oi0, ov1, oi1);
}

__device__ __forceinline__ uint32_t smem_u32(const void* p) {
    uint32_t a;
    asm("{ .reg .u64 t; cvta.to.shared.u64 t, %1; cvt.u32.u64 %0, t; }"
        : "=r"(a) : "l"(p));
    return a;
}

__device__ __forceinline__ void ldsm_x4(uint32_t& r0, uint32_t& r1,
                                        uint32_t& r2, uint32_t& r3,
                                        uint32_t addr) {
    asm volatile(
        "ldmatrix.sync.aligned.m8n8.x4.shared.b16 {%0, %1, %2, %3}, [%4];"
        : "=r"(r0), "=r"(r1), "=r"(r2), "=r"(r3) : "r"(addr));
}

__device__ __forceinline__ void mma_f16(float& c0, float& c1, float& c2, float& c3,
                                        uint32_t a0, uint32_t a1, uint32_t a2, uint32_t a3,
                                        uint32_t b0, uint32_t b1) {
    asm volatile(
        "mma.sync.aligned.m16n8k16.row.col.f32.f16.f16.f32 "
        "{%0, %1, %2, %3}, {%4, %5, %6, %7}, {%8, %9}, {%0, %1, %2, %3};"
        : "+f"(c0), "+f"(c1), "+f"(c2), "+f"(c3)
        : "r"(a0), "r"(a1), "r"(a2), "r"(a3), "r"(b0), "r"(b1));
}

__device__ __forceinline__ void cp_async16(uint32_t saddr, const void* gaddr) {
    asm volatile("cp.async.cg.shared.global [%0], [%1], 16;"
                 :: "r"(saddr), "l"(gaddr));
}
#define CP_COMMIT() asm volatile("cp.async.commit_group;" ::: "memory")
#define CP_WAIT0()  asm volatile("cp.async.wait_group 0;" ::: "memory")
#define CP_WAIT1()  asm volatile("cp.async.wait_group 1;" ::: "memory")

// ---------------- 1. normalize -> fp16 ---------------------------------------
__global__ void normhalf_k(const float* __restrict__ d0,
                           const float* __restrict__ d1) {
    int warp = (blockIdx.x * blockDim.x + threadIdx.x) >> 5;
    int lane = threadIdx.x & 31;
    const int total = BB * NN + BB * MM;
    if (warp >= total) return;

    const float* src;
    __half* dst;
    if (warp < BB * NN) {
        src = d0 + (size_t)warp * DD;
        dst = g_h0 + (size_t)warp * DD;
    } else {
        int w = warp - BB * NN;
        src = d1 + (size_t)w * DD;
        dst = g_h1 + (size_t)w * DD;
    }

    float4 v = *(const float4*)(src + lane * 4);
    float s = v.x * v.x + v.y * v.y + v.z * v.z + v.w * v.w;
#pragma unroll
    for (int off = 16; off > 0; off >>= 1)
        s += __shfl_xor_sync(0xFFFFFFFFu, s, off);
    float inv = 1.0f / fmaxf(sqrtf(s), 1e-12f);

    __half2* d2 = (__half2*)(dst + lane * 4);
    d2[0] = __floats2half2_rn(v.x * inv, v.y * inv);
    d2[1] = __floats2half2_rn(v.z * inv, v.w * inv);
}

// ---------------- 2. fp16 mma.sync GEMM, 2 tiles/CTA, reg-only epilogue -------
// One CTA = two 128x128 sim tiles sharing the same A block (128 rows of d0).
// 256 threads = 8 warps (2 x 4), 64x32 per warp per tile.
// SMEM: A(34KB) + B1(34KB) + B2(34KB) = 102KB -> 2 CTAs/SM. B2 prefetches via
// cp.async during tile 1's mainloop. Epilogue is register-only: shfl-butterfly
// row/col top-2 + small cross-warp partials in the dead B1 region; sim written
// directly from accumulators.
#define RS   272           // bytes per smem tile row (128 fp16 = 256B + 16B pad)
#define TILE_B (128 * RS)  // 34816 B per operand tile
#define OFF_A  0
#define OFF_B1 TILE_B
#define OFF_B2 (2 * TILE_B)
#define SMEM_BYTES (3 * TILE_B)   // 104448
// partial buffers live in the B1 region during epilogues (B1 dead post-main1;
// never touched by main2 which reads A + B2)
#define OFF_ROWP OFF_B1                       // 128 rows x 4 wn x 16B = 8192
#define OFF_COLP (OFF_B1 + 8192)              // 128 cols x 2 wm x 16B = 4096

__global__ __launch_bounds__(256, 2)
void gemm_tc_k(float* __restrict__ C) {
    extern __shared__ char smem[];
    uint32_t sb = smem_u32(smem);

    const int b     = blockIdx.z;
    const int tileN = blockIdx.y;
    const int n0 = tileN * 128;          // sim row block (A side, d0)
    const int tileM0 = blockIdx.x * 2;   // first of two column tiles

    const int tid  = threadIdx.x;
    const int wid  = tid >> 5;
    const int lane = tid & 31;
    const int wm   = wid >> 2;     // 0..1 : 64-row band
    const int wn   = wid & 3;      // 0..3 : 32-col band
    const int g    = lane >> 2;    // group id (row within 8)
    const int t    = lane & 3;     // thread-in-group (col pair)
    const int tile8 = lane >> 3;
    const int r8    = lane & 7;

    // lane-constant ldmatrix offsets (bytes) within a tile
    const uint32_t aoff = (uint32_t)(wm * 64 + (tile8 & 1) * 8 + r8) * RS
                        + (uint32_t)((tile8 >> 1) * 8) * 2;
    const uint32_t boff = (uint32_t)(wn * 32 + ((tile8 >> 1) & 1) * 8 + r8) * RS
                        + (uint32_t)((tile8 & 1) * 8) * 2;

    // ---- async loads: A + B1 (group 0), then B2 (group 1) --------------------
    {
        const char* srcA  = (const char*)(g_h0 + ((size_t)b * NN + n0) * DD);
        const char* srcB0 = (const char*)(g_h1 + ((size_t)b * MM + tileM0 * 128) * DD);
        const char* srcB1 = srcB0 + (size_t)128 * 256;
#pragma unroll
        for (int it = 0; it < 8; it++) {
            int f   = it * 256 + tid;
            int row = f >> 4;          // 16 slots per row
            int q   = f & 15;
            cp_async16(sb + OFF_A  + row * RS + q * 16, srcA  + (size_t)row * 256 + q * 16);
            cp_async16(sb + OFF_B1 + row * RS + q * 16, srcB0 + (size_t)row * 256 + q * 16);
        }
        CP_COMMIT();
#pragma unroll
        for (int it = 0; it < 8; it++) {
            int f   = it * 256 + tid;
            int row = f >> 4;
            int q   = f & 15;
            cp_async16(sb + OFF_B2 + row * RS + q * 16, srcB1 + (size_t)row * 256 + q * 16);
        }
        CP_COMMIT();
        CP_WAIT1();        // A + B1 landed; B2 still in flight
        __syncthreads();
    }

    float4* rowp = (float4*)(smem + OFF_ROWP);   // [row][wn]
    float4* colp = (float4*)(smem + OFF_COLP);   // [col][wm]

    // ---------------- per-tile body --------------------------------------------
    auto run_tile = [&](uint32_t bbase, int tileM) {
        const int m0 = tileM * 128;

        float acc[4][4][4];
#pragma unroll
        for (int mi = 0; mi < 4; mi++)
#pragma unroll
            for (int ni = 0; ni < 4; ni++)
#pragma unroll
                for (int c = 0; c < 4; c++) acc[mi][ni][c] = 0.0f;

        // ---- mainloop: 8 k-steps of 16 ----
#pragma unroll
        for (int ks = 0; ks < 8; ks++) {
            const uint32_t kb = ks * 32;

            uint32_t a[4][4];
#pragma unroll
            for (int mi = 0; mi < 4; mi++)
                ldsm_x4(a[mi][0], a[mi][1], a[mi][2], a[mi][3],
                        sb + OFF_A + aoff + mi * (16 * RS) + kb);

            uint32_t bf[4][2];
#pragma unroll
            for (int nh = 0; nh < 2; nh++) {
                uint32_t r0, r1, r2, r3;
                ldsm_x4(r0, r1, r2, r3, bbase + boff + nh * (16 * RS) + kb);
                bf[nh * 2 + 0][0] = r0; bf[nh * 2 + 0][1] = r1;
                bf[nh * 2 + 1][0] = r2; bf[nh * 2 + 1][1] = r3;
            }

#pragma unroll
            for (int mi = 0; mi < 4; mi++)
#pragma unroll
                for (int ni = 0; ni < 4; ni++)
                    mma_f16(acc[mi][ni][0], acc[mi][ni][1],
                            acc[mi][ni][2], acc[mi][ni][3],
                            a[mi][0], a[mi][1], a[mi][2], a[mi][3],
                            bf[ni][0], bf[ni][1]);
        }

        // ---- sim write: directly from accumulators (coalesced float2) --------
        {
            float* Cb = C + (size_t)b * NN * MM + (size_t)n0 * MM + m0;
#pragma unroll
            for (int mi = 0; mi < 4; mi++) {
                int r = wm * 64 + mi * 16 + g;
#pragma unroll
                for (int ni = 0; ni < 4; ni++) {
                    int c = wn * 32 + ni * 8 + 2 * t;
                    *(float2*)(Cb + (size_t)r * MM + c) =
                        make_float2(acc[mi][ni][0], acc[mi][ni][1]);
                    *(float2*)(Cb + (size_t)(r + 8) * MM + c) =
                        make_float2(acc[mi][ni][2], acc[mi][ni][3]);
                }
            }
        }

        // ---- row top-2 (in-register, butterfly over t-lanes) ------------------
        // each thread owns 8 row-slots (mi x half); per slot 8 col values
#pragma unroll
        for (int mi = 0; mi < 4; mi++) {
#pragma unroll
            for (int half = 0; half < 2; half++) {
                float v0 = -2.0f, v1 = -2.0f;
                int   i0 = -1,    i1 = -1;
#pragma unroll
                for (int ni = 0; ni < 4; ni++) {
                    int cbase = m0 + wn * 32 + ni * 8 + 2 * t;
                    push2(acc[mi][ni][half * 2 + 0], cbase,     v0, i0, v1, i1);
                    push2(acc[mi][ni][half * 2 + 1], cbase + 1, v0, i0, v1, i1);
                }
                bfly_merge(v0, i0, v1, i1, 1);
                bfly_merge(v0, i0, v1, i1, 2);
                if (t == 0) {
                    int r = wm * 64 + mi * 16 + half * 8 + g;   // 0..127
                    rowp[r * 4 + wn] =
                        make_float4(v0, v1, __int_as_float(i0), __int_as_float(i1));
                }
            }
        }

        // ---- col top-2 (in-register, butterfly over g-lanes) ------------------
        // each thread owns 8 columns (ni x cc); per col 8 row values
#pragma unroll
        for (int ni = 0; ni < 4; ni++) {
#pragma unroll
            for (int cc = 0; cc < 2; cc++) {
                float v0 = -2.0f, v1 = -2.0f;
                int   i0 = -1,    i1 = -1;
#pragma unroll
                for (int mi = 0; mi < 4; mi++) {
                    int rbase = n0 + wm * 64 + mi * 16 + g;
                    push2(acc[mi][ni][cc],     rbase,     v0, i0, v1, i1);
                    push2(acc[mi][ni][2 + cc], rbase + 8, v0, i0, v1, i1);
                }
                bfly_merge(v0, i0, v1, i1, 4);
                bfly_merge(v0, i0, v1, i1, 8);
                bfly_merge(v0, i0, v1, i1, 16);
                if (g == 0) {
                    int cl = wn * 32 + ni * 8 + 2 * t + cc;     // 0..127
                    colp[cl * 2 + wm] =
                        make_float4(v0, v1, __int_as_float(i0), __int_as_float(i1));
                }
            }
        }
        __syncthreads();

        // ---- final cross-warp merges + global partial write --------------------
        if (tid < 128) {
            int col = tid;
            float4 p0 = colp[col * 2 + 0];
            float4 p1 = colp[col * 2 + 1];
            float v0 = p0.x, v1 = p0.y;
            int   i0 = __float_as_int(p0.z), i1 = __float_as_int(p0.w);
            merge2(v0, i0, v1, i1, p1.x, __float_as_int(p1.z),
                                   p1.y, __float_as_int(p1.w));
            size_t o = ((size_t)b * MM + m0 + col) * NTILES + tileN;
            g_cp_v[o] = make_float2(v0, v1);
            g_cp_i[o] = make_int2(i0, i1);
        } else {
            int r = tid - 128;
            float4 p = rowp[r * 4 + 0];
            float v0 = p.x, v1 = p.y;
            int   i0 = __float_as_int(p.z), i1 = __float_as_int(p.w);
#pragma unroll
            for (int w = 1; w < 4; w++) {
                float4 q = rowp[r * 4 + w];
                merge2(v0, i0, v1, i1, q.x, __float_as_int(q.z),
                                       q.y, __float_as_int(q.w));
            }
            size_t o = ((size_t)b * NN + n0 + r) * NTILES + tileM;
            g_rp_v[o] = make_float2(v0, v1);
            g_rp_i[o] = make_int2(i0, i1);
        }
    };

    // tile 1 (B1), then tile 2 (B2, already prefetched)
    run_tile(sb + OFF_B1, tileM0);

    CP_WAIT0();          // B2 landed (long since, in steady state)
    __syncthreads();     // also orders epilogue-1 partial reads vs tile-2 reuse

    run_tile(sb + OFF_B2, tileM0 + 1);
}

// ---------------- 3. merge partials + thresholds ------------------------------
__global__ void merge_k() {
    int warp = (blockIdx.x * blockDim.x + threadIdx.x) >> 5;
    int lane = threadIdx.x & 31;
    const int nrows = BB * NN;
    if (warp >= nrows + BB * MM) return;

    float2 pv;
    int2   pi;
    if (warp < nrows) {
        pv = g_rp_v[(size_t)warp * NTILES + lane];
        pi = g_rp_i[(size_t)warp * NTILES + lane];
    } else {
        size_t w = warp - nrows;
        pv = g_cp_v[w * NTILES + lane];
        pi = g_cp_i[w * NTILES + lane];
    }
    float v0 = pv.x, v1 = pv.y;
    int   i0 = pi.x, i1 = pi.y;
#pragma unroll
    for (int off = 16; off > 0; off >>= 1) {
        float ov0 = __shfl_xor_sync(0xFFFFFFFFu, v0, off);
        float ov1 = __shfl_xor_sync(0xFFFFFFFFu, v1, off);
        int   oi0 = __shfl_xor_sync(0xFFFFFFFFu, i0, off);
        int   oi1 = __shfl_xor_sync(0xFFFFFFFFu, i1, off);
        merge2(v0, i0, v1, i1, ov0, oi0, ov1, oi1);
    }
    if (lane == 0) {
        float d0 = 2.0f * (1.0f - v0);
        float d1 = 2.0f * (1.0f - v1);
        bool ok = (d0 <= 0.64f * d1) && (d0 <= 0.49f);
        int m = ok ? i0 : -1;
        if (warp < nrows) g_m0raw[warp] = m;
        else              g_m1raw[warp - nrows] = m;
    }
}

// ---------------- 4. mutual check + output write -----------------------------
// out layout (fp32): matches0 [B*N] | matches1 [B*M] | mscores0 | mscores1 | sim
__global__ void mutual_k(float* __restrict__ out) {
    int idx = blockIdx.x * blockDim.x + threadIdx.x;
    if (idx >= BB * NN) return;
    int b = idx / NN;
    int n = idx - b * NN;

    int m0 = g_m0raw[idx];
    bool good0 = (m0 > -1) && (g_m1raw[b * MM + m0] == n);
    out[idx] = good0 ? (float)m0 : -1.0f;
    out[2 * BB * NN + idx] = good0 ? 1.0f : 0.0f;

    int m1 = g_m1raw[idx];
    bool good1 = (m1 > -1) && (g_m0raw[b * NN + m1] == n);
    out[BB * NN + idx] = good1 ? (float)m1 : -1.0f;
    out[3 * BB * NN + idx] = good1 ? 1.0f : 0.0f;
}

// ---------------- launch -----------------------------------------------------
extern "C" void kernel_launch(void* const* d_in, const int* in_sizes, int n_in,
                              void* d_out, int out_size) {
    const float* desc0 = (const float*)d_in[0];
    const float* desc1 = (const float*)d_in[1];
    float* out = (float*)d_out;
    float* sim = out + 4 * BB * NN;

    cudaFuncSetAttribute(gemm_tc_k,
                         cudaFuncAttributeMaxDynamicSharedMemorySize,
                         SMEM_BYTES);

    {
        int warps = BB * NN + BB * MM;
        normhalf_k<<<warps / 8, 256>>>(desc0, desc1);
    }
    {
        dim3 grid(MM / 256, NN / 128, BB);   // 2 column-tiles per CTA
        gemm_tc_k<<<grid, 256, SMEM_BYTES>>>(sim);
    }
    {
        int warps = 2 * BB * NN;
        merge_k<<<warps / 8, 256>>>();
    }
    {
        int t = BB * NN;
        mutual_k<<<(t + 255) / 256, 256>>>(out);
    }
}

// round 15
// speedup vs baseline: 1.0613x; 1.0613x over previous
#include <cuda_runtime.h>
#include <cuda_fp16.h>
#include <math.h>
#include <stdint.h>

#define BB 8
#define NN 4096
#define MM 4096
#define DD 128
#define NTILES 32          // 4096 / 128 tiles along each reduced dim

// ---------------- scratch (device globals: no allocation allowed) ----------
__device__ __half g_h0[BB * NN * DD];   // normalized descriptors0, fp16
__device__ __half g_h1[BB * MM * DD];   // normalized descriptors1, fp16

__device__ float2 g_rp_v[BB * NN * NTILES];
__device__ int2   g_rp_i[BB * NN * NTILES];
__device__ float2 g_cp_v[BB * MM * NTILES];
__device__ int2   g_cp_i[BB * MM * NTILES];

__device__ int    g_m0raw[BB * NN];
__device__ int    g_m1raw[BB * MM];

// ---------------- small helpers ---------------------------------------------
__device__ __forceinline__ void push2(float v, int i,
                                      float& v0, int& i0, float& v1, int& i1) {
    if (v > v0) { v1 = v0; i1 = i0; v0 = v; i0 = i; }
    else if (v > v1) { v1 = v; i1 = i; }
}

__device__ __forceinline__ bool better(float va, int ia, float vb, int ib) {
    return (va > vb) || (va == vb && ia < ib);
}

__device__ __forceinline__ void merge2(float& v0, int& i0, float& v1, int& i1,
                                       float ov0, int oi0, float ov1, int oi1) {
    if (better(ov0, oi0, v0, i0)) {
        if (better(v0, i0, ov1, oi1)) { v1 = v0; i1 = i0; }
        else                          { v1 = ov1; i1 = oi1; }
        v0 = ov0; i0 = oi0;
    } else {
        if (better(ov0, oi0, v1, i1)) { v1 = ov0; i1 = oi0; }
    }
}

__device__ __forceinline__ uint32_t smem_u32(const void* p) {
    uint32_t a;
    asm("{ .reg .u64 t; cvta.to.shared.u64 t, %1; cvt.u32.u64 %0, t; }"
        : "=r"(a) : "l"(p));
    return a;
}

__device__ __forceinline__ void ldsm_x4(uint32_t& r0, uint32_t& r1,
                                        uint32_t& r2, uint32_t& r3,
                                        uint32_t addr) {
    asm volatile(
        "ldmatrix.sync.aligned.m8n8.x4.shared.b16 {%0, %1, %2, %3}, [%4];"
        : "=r"(r0), "=r"(r1), "=r"(r2), "=r"(r3) : "r"(addr));
}

__device__ __forceinline__ void mma_f16(float& c0, float& c1, float& c2, float& c3,
                                        uint32_t a0, uint32_t a1, uint32_t a2, uint32_t a3,
                                        uint32_t b0, uint32_t b1) {
    asm volatile(
        "mma.sync.aligned.m16n8k16.row.col.f32.f16.f16.f32 "
        "{%0, %1, %2, %3}, {%4, %5, %6, %7}, {%8, %9}, {%0, %1, %2, %3};"
        : "+f"(c0), "+f"(c1), "+f"(c2), "+f"(c3)
        : "r"(a0), "r"(a1), "r"(a2), "r"(a3), "r"(b0), "r"(b1));
}

__device__ __forceinline__ void cp_async16(uint32_t saddr, const void* gaddr) {
    asm volatile("cp.async.cg.shared.global [%0], [%1], 16;"
                 :: "r"(saddr), "l"(gaddr));
}
#define CP_COMMIT() asm volatile("cp.async.commit_group;" ::: "memory")
#define CP_WAIT0()  asm volatile("cp.async.wait_group 0;" ::: "memory")

// ---------------- 1. normalize -> fp16 ---------------------------------------
__global__ void normhalf_k(const float* __restrict__ d0,
                           const float* __restrict__ d1) {
    int warp = (blockIdx.x * blockDim.x + threadIdx.x) >> 5;
    int lane = threadIdx.x & 31;
    const int total = BB * NN + BB * MM;
    if (warp >= total) return;

    const float* src;
    __half* dst;
    if (warp < BB * NN) {
        src = d0 + (size_t)warp * DD;
        dst = g_h0 + (size_t)warp * DD;
    } else {
        int w = warp - BB * NN;
        src = d1 + (size_t)w * DD;
        dst = g_h1 + (size_t)w * DD;
    }

    float4 v = *(const float4*)(src + lane * 4);
    float s = v.x * v.x + v.y * v.y + v.z * v.z + v.w * v.w;
#pragma unroll
    for (int off = 16; off > 0; off >>= 1)
        s += __shfl_xor_sync(0xFFFFFFFFu, s, off);
    float inv = 1.0f / fmaxf(sqrtf(s), 1e-12f);

    __half2* d2 = (__half2*)(dst + lane * 4);
    d2[0] = __floats2half2_rn(v.x * inv, v.y * inv);
    d2[1] = __floats2half2_rn(v.z * inv, v.w * inv);
}

// ---------------- 2. fp16 mma.sync GEMM tile + fused top-2 --------------------
// One CTA = one 128x128 sim tile. 256 threads = 8 warps (2 x 4), 64x32 per warp.
// Single K=128 block: A,B tiles 128 rows x 256B (+16B pad) = 34 KB each ->
// 68 KB SMEM, 2 CTAs/SM. Per k-step: 6 ldsm.x4 + 16 mma, 8 k-steps.
// Epilogue: sim written DIRECTLY from accumulators (STG overlaps what follows),
// then accs staged to SMEM (stride 130) for the fused row/col top-2 reductions.
#define RS   272           // bytes per smem tile row (128 fp16 = 256B + 16B pad)
#define TILE_B (128 * RS)  // 34816 B per operand tile
#define OFF_A 0
#define OFF_B TILE_B
#define SMEM_BYTES (2 * TILE_B)   // 69632
#define DSTR 130                   // fp32 staging row stride (floats)

__global__ __launch_bounds__(256, 2)
void gemm_tc_k(float* __restrict__ C) {
    extern __shared__ char smem[];
    uint32_t sb = smem_u32(smem);

    const int b     = blockIdx.z;
    const int tileN = blockIdx.y;
    const int tileM = blockIdx.x;
    const int n0 = tileN * 128;    // sim row block   (A side, d0)
    const int m0 = tileM * 128;    // sim col block   (B side, d1)

    const int tid  = threadIdx.x;
    const int wid  = tid >> 5;
    const int lane = tid & 31;
    const int wm   = wid >> 2;     // 0..1 : 64-row band
    const int wn   = wid & 3;      // 0..3 : 32-col band
    const int g    = lane >> 2;    // group id
    const int t    = lane & 3;     // thread-in-group
    const int tile8 = lane >> 3;
    const int r8    = lane & 7;

    // lane-constant ldmatrix offsets (bytes) within a tile
    const uint32_t aoff = (uint32_t)(wm * 64 + (tile8 & 1) * 8 + r8) * RS
                        + (uint32_t)((tile8 >> 1) * 8) * 2;
    const uint32_t boff = (uint32_t)(wn * 32 + ((tile8 >> 1) & 1) * 8 + r8) * RS
                        + (uint32_t)((tile8 & 1) * 8) * 2;

    float acc[4][4][4];            // [mi][ni][c]
#pragma unroll
    for (int mi = 0; mi < 4; mi++)
#pragma unroll
        for (int ni = 0; ni < 4; ni++)
#pragma unroll
            for (int c = 0; c < 4; c++) acc[mi][ni][c] = 0.0f;

    // ---- async load both operand tiles (whole K) -----------------------------
    {
        const char* srcA = (const char*)(g_h0 + ((size_t)b * NN + n0) * DD);
        const char* srcB = (const char*)(g_h1 + ((size_t)b * MM + m0) * DD);
        // 2048 16B slots per tile, 256 threads -> 8 per thread per tile
#pragma unroll
        for (int it = 0; it < 8; it++) {
            int f   = it * 256 + tid;
            int row = f >> 4;          // 16 slots per row
            int q   = f & 15;
            cp_async16(sb + OFF_A + row * RS + q * 16,
                       srcA + (size_t)row * 256 + q * 16);
            cp_async16(sb + OFF_B + row * RS + q * 16,
                       srcB + (size_t)row * 256 + q * 16);
        }
        CP_COMMIT();
        CP_WAIT0();
        __syncthreads();
    }

    // ---- mainloop: 8 k-steps of 16 --------------------------------------------
#pragma unroll
    for (int ks = 0; ks < 8; ks++) {
        const uint32_t kb = ks * 32;   // byte offset of this k-step

        // A fragments
        uint32_t a[4][4];
#pragma unroll
        for (int mi = 0; mi < 4; mi++)
            ldsm_x4(a[mi][0], a[mi][1], a[mi][2], a[mi][3],
                    sb + OFF_A + aoff + mi * (16 * RS) + kb);

        // B fragments
        uint32_t bf[4][2];
#pragma unroll
        for (int nh = 0; nh < 2; nh++) {
            uint32_t r0, r1, r2, r3;
            ldsm_x4(r0, r1, r2, r3,
                    sb + OFF_B + boff + nh * (16 * RS) + kb);
            bf[nh * 2 + 0][0] = r0; bf[nh * 2 + 0][1] = r1;
            bf[nh * 2 + 1][0] = r2; bf[nh * 2 + 1][1] = r3;
        }

#pragma unroll
        for (int mi = 0; mi < 4; mi++)
#pragma unroll
            for (int ni = 0; ni < 4; ni++)
                mma_f16(acc[mi][ni][0], acc[mi][ni][1],
                        acc[mi][ni][2], acc[mi][ni][3],
                        a[mi][0], a[mi][1], a[mi][2], a[mi][3],
                        bf[ni][0], bf[ni][1]);
    }

    // ---- sim write DIRECTLY from accumulators (fire-and-forget STG) -----------
    // mma fragment layout: row = band + mi*16 + g (+8), col = wn*32 + ni*8 + 2t.
    // Adjacent t-lanes cover 8-byte-aligned float2s; quarter-warps span 32B
    // segments x 4 rows -> 4x 32B sectors per warp-STG, fully coalesced per row.
    {
        float* Cb = C + (size_t)b * NN * MM + (size_t)n0 * MM + m0;
#pragma unroll
        for (int mi = 0; mi < 4; mi++) {
            int r = wm * 64 + mi * 16 + g;
#pragma unroll
            for (int ni = 0; ni < 4; ni++) {
                int c = wn * 32 + ni * 8 + 2 * t;
                *(float2*)(Cb + (size_t)r * MM + c) =
                    make_float2(acc[mi][ni][0], acc[mi][ni][1]);
                *(float2*)(Cb + (size_t)(r + 8) * MM + c) =
                    make_float2(acc[mi][ni][2], acc[mi][ni][3]);
            }
        }
    }

    __syncthreads();   // operand tiles dead; smem becomes fp32 staging

    // ---- stage accumulators to SMEM (fp32, stride DSTR) -----------------------
    float* dsm = (float*)smem;
#pragma unroll
    for (int mi = 0; mi < 4; mi++) {
        int r0 = wm * 64 + mi * 16 + g;
#pragma unroll
        for (int ni = 0; ni < 4; ni++) {
            int c0 = wn * 32 + ni * 8 + 2 * t;
            *(float2*)&dsm[r0 * DSTR + c0] =
                make_float2(acc[mi][ni][0], acc[mi][ni][1]);
            *(float2*)&dsm[(r0 + 8) * DSTR + c0] =
                make_float2(acc[mi][ni][2], acc[mi][ni][3]);
        }
    }
    __syncthreads();

    // ---- parallel reductions: threads 0-127 columns, 128-255 rows -------------
    if (tid < 128) {
        int col = tid;                       // sim column m0+col
        float v0 = -2.0f, v1 = -2.0f;
        int   i0 = -1,    i1 = -1;
#pragma unroll 4
        for (int r = 0; r < 128; r++)
            push2(dsm[r * DSTR + col], n0 + r, v0, i0, v1, i1);
        size_t o = ((size_t)b * MM + m0 + col) * NTILES + tileN;
        g_cp_v[o] = make_float2(v0, v1);
        g_cp_i[o] = make_int2(i0, i1);
    } else {
        int row = tid - 128;                 // sim row n0+row
        float v0 = -2.0f, v1 = -2.0f;
        int   i0 = -1,    i1 = -1;
#pragma unroll 4
        for (int c = 0; c < 128; c += 2) {
            float2 v = *(const float2*)&dsm[row * DSTR + c];
            push2(v.x, m0 + c,     v0, i0, v1, i1);
            push2(v.y, m0 + c + 1, v0, i0, v1, i1);
        }
        size_t o = ((size_t)b * NN + n0 + row) * NTILES + tileM;
        g_rp_v[o] = make_float2(v0, v1);
        g_rp_i[o] = make_int2(i0, i1);
    }
}

// ---------------- 3. merge partials + thresholds ------------------------------
__global__ void merge_k() {
    int warp = (blockIdx.x * blockDim.x + threadIdx.x) >> 5;
    int lane = threadIdx.x & 31;
    const int nrows = BB * NN;
    if (warp >= nrows + BB * MM) return;

    float2 pv;
    int2   pi;
    if (warp < nrows) {
        pv = g_rp_v[(size_t)warp * NTILES + lane];
        pi = g_rp_i[(size_t)warp * NTILES + lane];
    } else {
        size_t w = warp - nrows;
        pv = g_cp_v[w * NTILES + lane];
        pi = g_cp_i[w * NTILES + lane];
    }
    float v0 = pv.x, v1 = pv.y;
    int   i0 = pi.x, i1 = pi.y;
#pragma unroll
    for (int off = 16; off > 0; off >>= 1) {
        float ov0 = __shfl_xor_sync(0xFFFFFFFFu, v0, off);
        float ov1 = __shfl_xor_sync(0xFFFFFFFFu, v1, off);
        int   oi0 = __shfl_xor_sync(0xFFFFFFFFu, i0, off);
        int   oi1 = __shfl_xor_sync(0xFFFFFFFFu, i1, off);
        merge2(v0, i0, v1, i1, ov0, oi0, ov1, oi1);
    }
    if (lane == 0) {
        float d0 = 2.0f * (1.0f - v0);
        float d1 = 2.0f * (1.0f - v1);
        bool ok = (d0 <= 0.64f * d1) && (d0 <= 0.49f);
        int m = ok ? i0 : -1;
        if (warp < nrows) g_m0raw[warp] = m;
        else              g_m1raw[warp - nrows] = m;
    }
}

// ---------------- 4. mutual check + output write -----------------------------
// out layout (fp32): matches0 [B*N] | matches1 [B*M] | mscores0 | mscores1 | sim
__global__ void mutual_k(float* __restrict__ out) {
    int idx = blockIdx.x * blockDim.x + threadIdx.x;
    if (idx >= BB * NN) return;
    int b = idx / NN;
    int n = idx - b * NN;

    int m0 = g_m0raw[idx];
    bool good0 = (m0 > -1) && (g_m1raw[b * MM + m0] == n);
    out[idx] = good0 ? (float)m0 : -1.0f;
    out[2 * BB * NN + idx] = good0 ? 1.0f : 0.0f;

    int m1 = g_m1raw[idx];
    bool good1 = (m1 > -1) && (g_m0raw[b * NN + m1] == n);
    out[BB * NN + idx] = good1 ? (float)m1 : -1.0f;
    out[3 * BB * NN + idx] = good1 ? 1.0f : 0.0f;
}

// ---------------- launch -----------------------------------------------------
extern "C" void kernel_launch(void* const* d_in, const int* in_sizes, int n_in,
                              void* d_out, int out_size) {
    const float* desc0 = (const float*)d_in[0];
    const float* desc1 = (const float*)d_in[1];
    float* out = (float*)d_out;
    float* sim = out + 4 * BB * NN;

    cudaFuncSetAttribute(gemm_tc_k,
                         cudaFuncAttributeMaxDynamicSharedMemorySize,
                         SMEM_BYTES);

    {
        int warps = BB * NN + BB * MM;
        normhalf_k<<<warps / 8, 256>>>(desc0, desc1);
    }
    {
        dim3 grid(MM / 128, NN / 128, BB);
        gemm_tc_k<<<grid, 256, SMEM_BYTES>>>(sim);
    }
    {
        int warps = 2 * BB * NN;
        merge_k<<<warps / 8, 256>>>();
    }
    {
        int t = BB * NN;
        mutual_k<<<(t + 255) / 256, 256>>>(out);
    }
}